// round 16
// baseline (speedup 1.0000x reference)
#include <cuda_runtime.h>
#include <cuda_fp16.h>
#include <cstdint>

constexpr int Bc = 16, Qc = 2048, Kc = 2048, Dc = 128, DVc = 128;
constexpr int BQ = 128, BK = 64;
constexpr int KSTR = 136, VSTR = 72;   // smem strides in fp16 elems
constexpr float SCALE_L2 = 0.07216878364870323f * 1.4426950408889634f; // (1/sqrt192)*log2e

// ---- global scratch (prepass outputs) ----
__device__ __align__(16) float    g_ck  [Bc * Kc];
__device__ __align__(16) int      g_perm[Bc * Qc];
__device__ __align__(16) uint32_t g_kh  [Bc * Kc * Dc / 2];   // fp16 (no split)
__device__ __align__(16) uint32_t g_vth [Bc * DVc * Kc / 2];  // [b][dv][k/2] fp16

// ---- smem layout (bytes) — TRIPLE buffered K/V, ONE barrier per tile ----
constexpr int KBUF  = 64 * 272;                // 17408 per buffer
constexpr int VBUF  = 128 * 144;               // 18432 per buffer
constexpr int SM_K  = 0;                       // 3 bufs -> 52224
constexpr int SM_V  = 52224;                   // 3 bufs -> 55296 (end 107520)
constexpr int SM_CK = 107520;                  // [3][64] f32 = 768
constexpr int SM_PB = 108288;                  // perm [128] i32
constexpr int SM_VB = 108800;                  // vl   [128] i32
constexpr int SM_TOTAL = 109312;               // ~106.8 KB

// ---------------------------------------------------------------------------
__device__ __forceinline__ uint32_t pack_f16(float a, float b) {
    __half2 h = __floats2half2_rn(a, b);
    return *reinterpret_cast<uint32_t*>(&h);
}
__device__ __forceinline__ float f16lo(uint32_t p) {
    __half2 h = *reinterpret_cast<__half2*>(&p); return __low2float(h);
}
__device__ __forceinline__ float f16hi(uint32_t p) {
    __half2 h = *reinterpret_cast<__half2*>(&p); return __high2float(h);
}
// packed f16x2 exp2 — one MUFU op for two weights, result IS the P fragment
__device__ __forceinline__ uint32_t hex2(uint32_t x) {
    uint32_t r; asm("ex2.approx.f16x2 %0, %1;" : "=r"(r) : "r"(x)); return r;
}
__device__ __forceinline__ float2 h22f2(uint32_t p) {
    __half2 h = *reinterpret_cast<__half2*>(&p); return __half22float2(h);
}
__device__ __forceinline__ void mma16816(float c[4], const uint32_t a[4],
                                         uint32_t b0, uint32_t b1) {
    asm volatile(
        "mma.sync.aligned.m16n8k16.row.col.f32.f16.f16.f32 "
        "{%0,%1,%2,%3}, {%4,%5,%6,%7}, {%8,%9}, {%0,%1,%2,%3};\n"
        : "+f"(c[0]), "+f"(c[1]), "+f"(c[2]), "+f"(c[3])
        : "r"(a[0]), "r"(a[1]), "r"(a[2]), "r"(a[3]), "r"(b0), "r"(b1));
}
__device__ __forceinline__ void ldm_x4(uint32_t r[4], uint32_t addr) {
    asm volatile("ldmatrix.sync.aligned.m8n8.x4.shared.b16 {%0,%1,%2,%3}, [%4];"
        : "=r"(r[0]), "=r"(r[1]), "=r"(r[2]), "=r"(r[3]) : "r"(addr));
}
__device__ __forceinline__ void cp_async16(void* s, const void* g) {
    uint32_t sa = (uint32_t)__cvta_generic_to_shared(s);
    asm volatile("cp.async.cg.shared.global [%0], [%1], 16;\n" :: "r"(sa), "l"(g));
}
__device__ __forceinline__ void cp_commit() { asm volatile("cp.async.commit_group;\n"); }

// ---------------------------------------------------------------------------
// FUSED prepass. Block roles by blockIdx.x:
//   [0, 2048)     : V transpose + fp16 convert (tile 64k x 32dv)
//   [2048, 6144)  : K rows -> fp16 + ck bias (8 warps/block, warp = row)
//   [6144, 6160)  : per-batch counting sort of queries by len bucket
constexpr int PREP_K0 = 2048, PREP_P0 = 6144;
constexpr int PREP_GRID = 6160;

__global__ __launch_bounds__(256, 1)
void prep_kernel(const float* __restrict__ Km, const float* __restrict__ Vm,
                 const int* __restrict__ vlen) {
    const int bid = blockIdx.x;
    const int tid = threadIdx.x;

    if (bid < PREP_K0) {
        __shared__ float tile[64][33];
        int b = bid >> 7, rem = bid & 127;
        int dv0 = (rem >> 5) * 32, k0 = (rem & 31) * 64;
        #pragma unroll
        for (int i = 0; i < 8; i++) {
            int idx = tid + i * 256;
            int r = idx >> 5, c = idx & 31;
            tile[r][c] = Vm[((size_t)b * Kc + k0 + r) * DVc + dv0 + c];
        }
        __syncthreads();
        #pragma unroll
        for (int i = 0; i < 4; i++) {
            int idx = tid + i * 256;
            int dv = idx >> 5, kp = idx & 31;
            size_t o = ((size_t)b * DVc + dv0 + dv) * (Kc / 2) + k0 / 2 + kp;
            g_vth[o] = pack_f16(tile[2 * kp][dv], tile[2 * kp + 1][dv]);
        }
    } else if (bid < PREP_P0) {
        int row  = (bid - PREP_K0) * 8 + (tid >> 5);
        int lane = tid & 31;
        float4 x = *(const float4*)(Km + (size_t)row * Dc + lane * 4);
        g_kh[(size_t)row * 64 + lane * 2]     = pack_f16(x.x, x.y);
        g_kh[(size_t)row * 64 + lane * 2 + 1] = pack_f16(x.z, x.w);
        float ss = x.x * x.x + x.y * x.y + x.z * x.z + x.w * x.w;
        #pragma unroll
        for (int o = 16; o > 0; o >>= 1) ss += __shfl_xor_sync(0xffffffffu, ss, o);
        if (lane == 0)
            g_ck[row] = (0.5f * (float)Dc - 0.5f * ss) * SCALE_L2;
    } else {
        __shared__ int hist[32], offs[32];
        const int b = bid - PREP_P0;
        if (tid < 32) hist[tid] = 0;
        __syncthreads();
        int lens[8];
        #pragma unroll
        for (int i = 0; i < 8; i++) {
            lens[i] = vlen[(size_t)b * Qc + tid * 8 + i];
            atomicAdd(&hist[(lens[i] - 1) >> 6], 1);
        }
        __syncthreads();
        if (tid == 0) {
            int s = 0;
            #pragma unroll
            for (int j = 0; j < 32; j++) { offs[j] = s; s += hist[j]; }
        }
        __syncthreads();
        #pragma unroll
        for (int i = 0; i < 8; i++) {
            int pos = atomicAdd(&offs[(lens[i] - 1) >> 6], 1);
            g_perm[(size_t)b * Qc + pos] = tid * 8 + i;
        }
    }
}

// ---------------------------------------------------------------------------
extern __shared__ char smraw[];

__global__ __launch_bounds__(256, 1)
void attn_kernel(const float* __restrict__ Qm, const int* __restrict__ vlen,
                 float* __restrict__ Om) {
    int* pbuf  = (int*)(smraw + SM_PB);
    int* vlbuf = (int*)(smraw + SM_VB);

    const int tid  = threadIdx.x;
    const int lane = tid & 31;
    const int warp = tid >> 5;
    const int g    = lane >> 2;
    const int t4   = lane & 3;
    // LPT: batch on x (fast bid dim), REVERSED q-tile on y (longest first).
    const int b    = blockIdx.x;
    const int q0   = (gridDim.y - 1 - blockIdx.y) * BQ;

    if (tid < BQ) pbuf[tid] = g_perm[(size_t)b * Qc + q0 + tid];
    __syncthreads();
    if (tid < BQ) vlbuf[tid] = vlen[(size_t)b * Qc + pbuf[tid]];

    const uint32_t* kh_g = g_kh  + (size_t)b * Kc * 64;
    const uint32_t* vh_g = g_vth + (size_t)b * DVc * (Kc / 2);
    const float*    ck_g = g_ck + (size_t)b * Kc;

    // ---- prefetch tile0 K/V + ck0 ----
    #pragma unroll
    for (int i = 0; i < 4; i++) {
        int idx = tid + i * 256;
        int row = idx >> 4, ch = idx & 15;
        cp_async16(smraw + SM_K + row * 272 + ch * 16, kh_g + row * 64 + ch * 4);
        int dv = idx >> 3, vch = idx & 7;
        cp_async16(smraw + SM_V + dv * 144 + vch * 16, vh_g + (size_t)dv * 1024 + vch * 4);
    }
    if (tid < 16)
        cp_async16(smraw + SM_CK + tid * 16, ck_g + tid * 4);
    cp_commit();

    __syncthreads();
    const int n_tiles = ((vlbuf[BQ - 1] - 1) >> 6) + 1;
    const int vl0 = vlbuf[warp * 16 + g];
    const int vl1 = vlbuf[warp * 16 + g + 8];
    const int vlmin = min(vl0, vl1);
    const int prow0 = pbuf[warp * 16 + g];
    const int prow1 = pbuf[warp * 16 + g + 8];

    // ---- Q fragments register-resident (from f32 gmem, split hi/lo) ----
    uint32_t qh[8][4], ql[8][4];
    {
        const float* q0g = Qm + ((size_t)b * Qc + prow0) * Dc;
        const float* q1g = Qm + ((size_t)b * Qc + prow1) * Dc;
        #pragma unroll
        for (int kc = 0; kc < 8; kc++) {
            int col = kc * 16 + t4 * 2;
            float2 x0 = *(const float2*)(q0g + col);
            float2 x1 = *(const float2*)(q1g + col);
            float2 x2 = *(const float2*)(q0g + col + 8);
            float2 x3 = *(const float2*)(q1g + col + 8);
            qh[kc][0] = pack_f16(x0.x, x0.y);
            qh[kc][1] = pack_f16(x1.x, x1.y);
            qh[kc][2] = pack_f16(x2.x, x2.y);
            qh[kc][3] = pack_f16(x3.x, x3.y);
            ql[kc][0] = pack_f16(x0.x - f16lo(qh[kc][0]), x0.y - f16hi(qh[kc][0]));
            ql[kc][1] = pack_f16(x1.x - f16lo(qh[kc][1]), x1.y - f16hi(qh[kc][1]));
            ql[kc][2] = pack_f16(x2.x - f16lo(qh[kc][2]), x2.y - f16hi(qh[kc][2]));
            ql[kc][3] = pack_f16(x3.x - f16lo(qh[kc][3]), x3.y - f16hi(qh[kc][3]));
        }
    }

    // ---- ldmatrix per-lane byte offsets (K/V) ----
    const int mi = lane >> 3, r8 = lane & 7;
    const uint32_t smem_u = (uint32_t)__cvta_generic_to_shared(smraw);
    const uint32_t k_lane = (((mi >> 1) * 8 + r8) * KSTR + (mi & 1) * 8) * 2;
    const uint32_t v_lane = (((mi >> 1) * 8 + r8) * VSTR + (mi & 1) * 8) * 2;

    // no online max: |s*log2e| bounded (~±8); masked scores pack to -inf in
    // f16 and ex2 gives exactly +0.
    float l0 = 0.0f, l1 = 0.0f;
    float o[16][4];
    #pragma unroll
    for (int nb = 0; nb < 16; nb++)
        #pragma unroll
        for (int r = 0; r < 4; r++) o[nb][r] = 0.0f;

    int c = 0, cn = 1;   // triple-buffer cursors

    for (int t = 0; t < n_tiles; t++) {
        if (t + 1 < n_tiles) {
            const int k0n = (t + 1) * BK;
            #pragma unroll
            for (int i = 0; i < 4; i++) {
                int idx = tid + i * 256;
                int row = idx >> 4, ch = idx & 15;
                cp_async16(smraw + SM_K + cn * KBUF + row * 272 + ch * 16,
                           kh_g + (size_t)(k0n + row) * 64 + ch * 4);
                int dv = idx >> 3, vch = idx & 7;
                cp_async16(smraw + SM_V + cn * VBUF + dv * 144 + vch * 16,
                           vh_g + (size_t)dv * 1024 + k0n / 2 + vch * 4);
            }
            if (tid < 16)
                cp_async16(smraw + SM_CK + cn * 256 + tid * 16, ck_g + k0n + tid * 4);
            cp_commit();
            asm volatile("cp.async.wait_group 1;\n" ::: "memory");
        } else {
            asm volatile("cp.async.wait_group 0;\n" ::: "memory");
        }
        // ONE barrier per tile (triple buffering makes it sufficient).
        __syncthreads();

        const uint32_t kh_base = smem_u + SM_K + c * KBUF + k_lane;
        const uint32_t vh_base = smem_u + SM_V + c * VBUF + v_lane;
        const float*   ckb     = (const float*)(smraw + SM_CK) + c * 64;
        const int k0 = t * BK;

        // ---- S = Q K^T : A-side split fp16 (Q in registers), K plain fp16 ----
        float s[8][4];
        #pragma unroll
        for (int j = 0; j < 8; j++)
            #pragma unroll
            for (int r = 0; r < 4; r++) s[j][r] = 0.0f;

        #pragma unroll
        for (int kc = 0; kc < 8; kc++) {
            uint32_t bh[4][4];
            #pragma unroll
            for (int jp = 0; jp < 4; jp++)
                ldm_x4(bh[jp], kh_base + (uint32_t)(jp * 16 * KSTR + kc * 16) * 2);
            #pragma unroll
            for (int jp = 0; jp < 4; jp++) {
                mma16816(s[2 * jp],     qh[kc], bh[jp][0], bh[jp][1]);
                mma16816(s[2 * jp + 1], qh[kc], bh[jp][2], bh[jp][3]);
            }
            #pragma unroll
            for (int jp = 0; jp < 4; jp++) {
                mma16816(s[2 * jp],     ql[kc], bh[jp][0], bh[jp][1]);
                mma16816(s[2 * jp + 1], ql[kc], bh[jp][2], bh[jp][3]);
            }
        }

        // ---- softmax (scalar l, same arithmetic/order as R13) interleaved
        //      with PV groups so MUFU latency hides behind HMMAs.
        //      ph[kk] is complete after softmax pairs j=2kk, 2kk+1. ----
        uint32_t ph[4][4];
        const bool full = (k0 + BK <= vlmin);
        #pragma unroll
        for (int kk = 0; kk < 4; kk++) {
            // softmax pair-columns j = 2kk, 2kk+1 -> fills ph[kk]
            #pragma unroll
            for (int jj = 0; jj < 2; jj++) {
                const int j = 2 * kk + jj;
                float2 ckj = *(float2*)&ckb[j * 8 + t4 * 2];
                float s0, s1, s2, s3;
                if (full) {
                    s0 = s[j][0] * SCALE_L2 + ckj.x;
                    s1 = s[j][1] * SCALE_L2 + ckj.y;
                    s2 = s[j][2] * SCALE_L2 + ckj.x;
                    s3 = s[j][3] * SCALE_L2 + ckj.y;
                } else {
                    int col = k0 + j * 8 + t4 * 2;
                    s0 = (col     < vl0) ? s[j][0] * SCALE_L2 + ckj.x : -1e6f;
                    s1 = (col + 1 < vl0) ? s[j][1] * SCALE_L2 + ckj.y : -1e6f;
                    s2 = (col     < vl1) ? s[j][2] * SCALE_L2 + ckj.x : -1e6f;
                    s3 = (col + 1 < vl1) ? s[j][3] * SCALE_L2 + ckj.y : -1e6f;
                }
                uint32_t e01 = hex2(pack_f16(s0, s1));
                uint32_t e23 = hex2(pack_f16(s2, s3));
                ph[kk][jj * 2]     = e01;
                ph[kk][jj * 2 + 1] = e23;
                float2 f01 = h22f2(e01), f23 = h22f2(e23);
                l0 += f01.x + f01.y;
                l1 += f23.x + f23.y;
            }
            // PV group kk — consumes ph[kk], overlaps with softmax of kk+1
            #pragma unroll
            for (int np = 0; np < 8; np++) {
                uint32_t bh[4];
                ldm_x4(bh, vh_base + (uint32_t)(np * 16 * VSTR + kk * 16) * 2);
                mma16816(o[2 * np],     ph[kk], bh[0], bh[1]);
                mma16816(o[2 * np + 1], ph[kk], bh[2], bh[3]);
            }
        }

        c  = (c  == 2) ? 0 : c + 1;
        cn = (cn == 2) ? 0 : cn + 1;
    }

    // ---- epilogue: reduce l across the quad, scatter to original rows ----
    l0 += __shfl_xor_sync(0xffffffffu, l0, 1);
    l0 += __shfl_xor_sync(0xffffffffu, l0, 2);
    l1 += __shfl_xor_sync(0xffffffffu, l1, 1);
    l1 += __shfl_xor_sync(0xffffffffu, l1, 2);
    float il0 = 1.0f / l0, il1 = 1.0f / l1;
    #pragma unroll
    for (int nb = 0; nb < 16; nb++) {
        int dv = nb * 8 + t4 * 2;
        float2 w0 = make_float2(o[nb][0] * il0, o[nb][1] * il0);
        float2 w1 = make_float2(o[nb][2] * il1, o[nb][3] * il1);
        *(float2*)&Om[((size_t)b * Qc + prow0) * DVc + dv] = w0;
        *(float2*)&Om[((size_t)b * Qc + prow1) * DVc + dv] = w1;
    }
}

// ---------------------------------------------------------------------------
extern "C" void kernel_launch(void* const* d_in, const int* in_sizes, int n_in,
                              void* d_out, int out_size) {
    const float* q  = (const float*)d_in[0];
    const float* k  = (const float*)d_in[1];
    const float* v  = (const float*)d_in[2];
    const int*   vl = (const int*)d_in[3];
    float*       o  = (float*)d_out;

    cudaFuncSetAttribute(attn_kernel, cudaFuncAttributeMaxDynamicSharedMemorySize, SM_TOTAL);

    prep_kernel<<<PREP_GRID, 256>>>(k, v, vl);

    dim3 grid(Bc, Qc / BQ);   // x = batch (fast bid dim), y = reversed q-tile (LPT)
    attn_kernel<<<grid, 256, SM_TOTAL>>>(q, vl, o);
}

// round 17
// speedup vs baseline: 1.2306x; 1.2306x over previous
#include <cuda_runtime.h>
#include <cuda_fp16.h>
#include <cstdint>

constexpr int Bc = 16, Qc = 2048, Kc = 2048, Dc = 128, DVc = 128;
constexpr int BQ = 128, BK = 64;
constexpr int KSTR = 136, VSTR = 72;   // smem strides in fp16 elems
constexpr float SCALE_L2 = 0.07216878364870323f * 1.4426950408889634f; // (1/sqrt192)*log2e

// ---- global scratch (prepass outputs) ----
__device__ __align__(16) float    g_ck  [Bc * Kc];
__device__ __align__(16) int      g_perm[Bc * Qc];
__device__ __align__(16) uint32_t g_kh  [Bc * Kc * Dc / 2];   // fp16 (no split)
__device__ __align__(16) uint32_t g_vth [Bc * DVc * Kc / 2];  // [b][dv][k/2] fp16

// ---- smem layout (bytes) — TRIPLE buffered K/V, ONE barrier per tile ----
constexpr int KBUF  = 64 * 272;                // 17408 per buffer
constexpr int VBUF  = 128 * 144;               // 18432 per buffer
constexpr int SM_K  = 0;                       // 3 bufs -> 52224
constexpr int SM_V  = 52224;                   // 3 bufs -> 55296 (end 107520)
constexpr int SM_CK = 107520;                  // [3][64] f32 = 768
constexpr int SM_PB = 108288;                  // perm [128] i32
constexpr int SM_VB = 108800;                  // vl   [128] i32
constexpr int SM_TOTAL = 109312;               // ~106.8 KB

// ---------------------------------------------------------------------------
__device__ __forceinline__ uint32_t pack_f16(float a, float b) {
    __half2 h = __floats2half2_rn(a, b);
    return *reinterpret_cast<uint32_t*>(&h);
}
// packed f16x2 exp2 — one MUFU op for two weights, result IS the P fragment
__device__ __forceinline__ uint32_t hex2(uint32_t x) {
    uint32_t r; asm("ex2.approx.f16x2 %0, %1;" : "=r"(r) : "r"(x)); return r;
}
__device__ __forceinline__ float2 h22f2(uint32_t p) {
    __half2 h = *reinterpret_cast<__half2*>(&p); return __half22float2(h);
}
__device__ __forceinline__ void mma16816(float c[4], const uint32_t a[4],
                                         uint32_t b0, uint32_t b1) {
    asm volatile(
        "mma.sync.aligned.m16n8k16.row.col.f32.f16.f16.f32 "
        "{%0,%1,%2,%3}, {%4,%5,%6,%7}, {%8,%9}, {%0,%1,%2,%3};\n"
        : "+f"(c[0]), "+f"(c[1]), "+f"(c[2]), "+f"(c[3])
        : "r"(a[0]), "r"(a[1]), "r"(a[2]), "r"(a[3]), "r"(b0), "r"(b1));
}
__device__ __forceinline__ void ldm_x4(uint32_t r[4], uint32_t addr) {
    asm volatile("ldmatrix.sync.aligned.m8n8.x4.shared.b16 {%0,%1,%2,%3}, [%4];"
        : "=r"(r[0]), "=r"(r[1]), "=r"(r[2]), "=r"(r[3]) : "r"(addr));
}
__device__ __forceinline__ void cp_async16(void* s, const void* g) {
    uint32_t sa = (uint32_t)__cvta_generic_to_shared(s);
    asm volatile("cp.async.cg.shared.global [%0], [%1], 16;\n" :: "r"(sa), "l"(g));
}
__device__ __forceinline__ void cp_commit() { asm volatile("cp.async.commit_group;\n"); }

// ---------------------------------------------------------------------------
// FUSED prepass. Block roles by blockIdx.x:
//   [0, 2048)     : V transpose + fp16 convert (tile 64k x 32dv)
//   [2048, 6144)  : K rows -> fp16 + ck bias (8 warps/block, warp = row)
//   [6144, 6160)  : per-batch counting sort of queries by len bucket
constexpr int PREP_K0 = 2048, PREP_P0 = 6144;
constexpr int PREP_GRID = 6160;

__global__ __launch_bounds__(256, 1)
void prep_kernel(const float* __restrict__ Km, const float* __restrict__ Vm,
                 const int* __restrict__ vlen) {
    const int bid = blockIdx.x;
    const int tid = threadIdx.x;

    if (bid < PREP_K0) {
        __shared__ float tile[64][33];
        int b = bid >> 7, rem = bid & 127;
        int dv0 = (rem >> 5) * 32, k0 = (rem & 31) * 64;
        #pragma unroll
        for (int i = 0; i < 8; i++) {
            int idx = tid + i * 256;
            int r = idx >> 5, c = idx & 31;
            tile[r][c] = Vm[((size_t)b * Kc + k0 + r) * DVc + dv0 + c];
        }
        __syncthreads();
        #pragma unroll
        for (int i = 0; i < 4; i++) {
            int idx = tid + i * 256;
            int dv = idx >> 5, kp = idx & 31;
            size_t o = ((size_t)b * DVc + dv0 + dv) * (Kc / 2) + k0 / 2 + kp;
            g_vth[o] = pack_f16(tile[2 * kp][dv], tile[2 * kp + 1][dv]);
        }
    } else if (bid < PREP_P0) {
        int row  = (bid - PREP_K0) * 8 + (tid >> 5);
        int lane = tid & 31;
        float4 x = *(const float4*)(Km + (size_t)row * Dc + lane * 4);
        g_kh[(size_t)row * 64 + lane * 2]     = pack_f16(x.x, x.y);
        g_kh[(size_t)row * 64 + lane * 2 + 1] = pack_f16(x.z, x.w);
        float ss = x.x * x.x + x.y * x.y + x.z * x.z + x.w * x.w;
        #pragma unroll
        for (int o = 16; o > 0; o >>= 1) ss += __shfl_xor_sync(0xffffffffu, ss, o);
        if (lane == 0)
            g_ck[row] = (0.5f * (float)Dc - 0.5f * ss) * SCALE_L2;
    } else {
        __shared__ int hist[32], offs[32];
        const int b = bid - PREP_P0;
        if (tid < 32) hist[tid] = 0;
        __syncthreads();
        int lens[8];
        #pragma unroll
        for (int i = 0; i < 8; i++) {
            lens[i] = vlen[(size_t)b * Qc + tid * 8 + i];
            atomicAdd(&hist[(lens[i] - 1) >> 6], 1);
        }
        __syncthreads();
        if (tid == 0) {
            int s = 0;
            #pragma unroll
            for (int j = 0; j < 32; j++) { offs[j] = s; s += hist[j]; }
        }
        __syncthreads();
        #pragma unroll
        for (int i = 0; i < 8; i++) {
            int pos = atomicAdd(&offs[(lens[i] - 1) >> 6], 1);
            g_perm[(size_t)b * Qc + pos] = tid * 8 + i;
        }
    }
}

// ---------------------------------------------------------------------------
extern __shared__ char smraw[];

__global__ __launch_bounds__(256, 1)
void attn_kernel(const float* __restrict__ Qm, const int* __restrict__ vlen,
                 float* __restrict__ Om) {
    int* pbuf  = (int*)(smraw + SM_PB);
    int* vlbuf = (int*)(smraw + SM_VB);

    const int tid  = threadIdx.x;
    const int lane = tid & 31;
    const int warp = tid >> 5;
    const int g    = lane >> 2;
    const int t4   = lane & 3;
    // LPT: batch on x (fast bid dim), REVERSED q-tile on y (longest first).
    const int b    = blockIdx.x;
    const int q0   = (gridDim.y - 1 - blockIdx.y) * BQ;

    if (tid < BQ) pbuf[tid] = g_perm[(size_t)b * Qc + q0 + tid];
    __syncthreads();
    if (tid < BQ) vlbuf[tid] = vlen[(size_t)b * Qc + pbuf[tid]];

    const uint32_t* kh_g = g_kh  + (size_t)b * Kc * 64;
    const uint32_t* vh_g = g_vth + (size_t)b * DVc * (Kc / 2);
    const float*    ck_g = g_ck + (size_t)b * Kc;

    // ---- prefetch tile0 K/V + ck0 ----
    #pragma unroll
    for (int i = 0; i < 4; i++) {
        int idx = tid + i * 256;
        int row = idx >> 4, ch = idx & 15;
        cp_async16(smraw + SM_K + row * 272 + ch * 16, kh_g + row * 64 + ch * 4);
        int dv = idx >> 3, vch = idx & 7;
        cp_async16(smraw + SM_V + dv * 144 + vch * 16, vh_g + (size_t)dv * 1024 + vch * 4);
    }
    if (tid < 16)
        cp_async16(smraw + SM_CK + tid * 16, ck_g + tid * 4);
    cp_commit();

    __syncthreads();
    const int n_tiles = ((vlbuf[BQ - 1] - 1) >> 6) + 1;
    const int vl0 = vlbuf[warp * 16 + g];
    const int vl1 = vlbuf[warp * 16 + g + 8];
    const int vlmin = min(vl0, vl1);
    const int prow0 = pbuf[warp * 16 + g];
    const int prow1 = pbuf[warp * 16 + g + 8];

    // ---- Q fragments register-resident (plain fp16, no split) ----
    uint32_t qh[8][4];
    {
        const float* q0g = Qm + ((size_t)b * Qc + prow0) * Dc;
        const float* q1g = Qm + ((size_t)b * Qc + prow1) * Dc;
        #pragma unroll
        for (int kc = 0; kc < 8; kc++) {
            int col = kc * 16 + t4 * 2;
            float2 x0 = *(const float2*)(q0g + col);
            float2 x1 = *(const float2*)(q1g + col);
            float2 x2 = *(const float2*)(q0g + col + 8);
            float2 x3 = *(const float2*)(q1g + col + 8);
            qh[kc][0] = pack_f16(x0.x, x0.y);
            qh[kc][1] = pack_f16(x1.x, x1.y);
            qh[kc][2] = pack_f16(x2.x, x2.y);
            qh[kc][3] = pack_f16(x3.x, x3.y);
        }
    }

    // ---- ldmatrix per-lane byte offsets (K/V) ----
    const int mi = lane >> 3, r8 = lane & 7;
    const uint32_t smem_u = (uint32_t)__cvta_generic_to_shared(smraw);
    const uint32_t k_lane = (((mi >> 1) * 8 + r8) * KSTR + (mi & 1) * 8) * 2;
    const uint32_t v_lane = (((mi >> 1) * 8 + r8) * VSTR + (mi & 1) * 8) * 2;

    // no online max: |s*log2e| bounded (~±8); masked scores pack to -inf in
    // f16 and ex2 gives exactly +0.
    float l0 = 0.0f, l1 = 0.0f;
    float o[16][4];
    #pragma unroll
    for (int nb = 0; nb < 16; nb++)
        #pragma unroll
        for (int r = 0; r < 4; r++) o[nb][r] = 0.0f;

    int c = 0, cn = 1;   // triple-buffer cursors

    for (int t = 0; t < n_tiles; t++) {
        if (t + 1 < n_tiles) {
            const int k0n = (t + 1) * BK;
            #pragma unroll
            for (int i = 0; i < 4; i++) {
                int idx = tid + i * 256;
                int row = idx >> 4, ch = idx & 15;
                cp_async16(smraw + SM_K + cn * KBUF + row * 272 + ch * 16,
                           kh_g + (size_t)(k0n + row) * 64 + ch * 4);
                int dv = idx >> 3, vch = idx & 7;
                cp_async16(smraw + SM_V + cn * VBUF + dv * 144 + vch * 16,
                           vh_g + (size_t)dv * 1024 + k0n / 2 + vch * 4);
            }
            if (tid < 16)
                cp_async16(smraw + SM_CK + cn * 256 + tid * 16, ck_g + k0n + tid * 4);
            cp_commit();
            asm volatile("cp.async.wait_group 1;\n" ::: "memory");
        } else {
            asm volatile("cp.async.wait_group 0;\n" ::: "memory");
        }
        // ONE barrier per tile (triple buffering makes it sufficient).
        __syncthreads();

        const uint32_t kh_base = smem_u + SM_K + c * KBUF + k_lane;
        const uint32_t vh_base = smem_u + SM_V + c * VBUF + v_lane;
        const float*   ckb     = (const float*)(smraw + SM_CK) + c * 64;
        const int k0 = t * BK;

        // ---- S = Q K^T : single-term fp16 (Q in registers), K plain fp16 ----
        float s[8][4];
        #pragma unroll
        for (int j = 0; j < 8; j++)
            #pragma unroll
            for (int r = 0; r < 4; r++) s[j][r] = 0.0f;

        #pragma unroll
        for (int kc = 0; kc < 8; kc++) {
            uint32_t bh[4][4];
            #pragma unroll
            for (int jp = 0; jp < 4; jp++)
                ldm_x4(bh[jp], kh_base + (uint32_t)(jp * 16 * KSTR + kc * 16) * 2);
            #pragma unroll
            for (int jp = 0; jp < 4; jp++) {
                mma16816(s[2 * jp],     qh[kc], bh[jp][0], bh[jp][1]);
                mma16816(s[2 * jp + 1], qh[kc], bh[jp][2], bh[jp][3]);
            }
        }

        // ---- scale + bias; exp2 in packed f16x2; result IS the P fragment ----
        uint32_t ph[4][4];
        if (k0 + BK <= vlmin) {
            #pragma unroll
            for (int j = 0; j < 8; j++) {
                float2 ckj = *(float2*)&ckb[j * 8 + t4 * 2];
                float s0 = s[j][0] * SCALE_L2 + ckj.x;
                float s1 = s[j][1] * SCALE_L2 + ckj.y;
                float s2 = s[j][2] * SCALE_L2 + ckj.x;
                float s3 = s[j][3] * SCALE_L2 + ckj.y;
                uint32_t e01 = hex2(pack_f16(s0, s1));
                uint32_t e23 = hex2(pack_f16(s2, s3));
                int kk = j >> 1, hh = (j & 1) * 2;
                ph[kk][hh]     = e01;
                ph[kk][hh + 1] = e23;
                float2 f01 = h22f2(e01), f23 = h22f2(e23);
                l0 += f01.x + f01.y;
                l1 += f23.x + f23.y;
            }
        } else {
            #pragma unroll
            for (int j = 0; j < 8; j++) {
                float2 ckj = *(float2*)&ckb[j * 8 + t4 * 2];
                int col = k0 + j * 8 + t4 * 2;
                float s0 = (col     < vl0) ? s[j][0] * SCALE_L2 + ckj.x : -1e6f;
                float s1 = (col + 1 < vl0) ? s[j][1] * SCALE_L2 + ckj.y : -1e6f;
                float s2 = (col     < vl1) ? s[j][2] * SCALE_L2 + ckj.x : -1e6f;
                float s3 = (col + 1 < vl1) ? s[j][3] * SCALE_L2 + ckj.y : -1e6f;
                uint32_t e01 = hex2(pack_f16(s0, s1));
                uint32_t e23 = hex2(pack_f16(s2, s3));
                int kk = j >> 1, hh = (j & 1) * 2;
                ph[kk][hh]     = e01;
                ph[kk][hh + 1] = e23;
                float2 f01 = h22f2(e01), f23 = h22f2(e23);
                l0 += f01.x + f01.y;
                l1 += f23.x + f23.y;
            }
        }

        // ---- O += P V : single-term fp16 P, V plain fp16 ----
        #pragma unroll
        for (int kk = 0; kk < 4; kk++) {
            #pragma unroll
            for (int np = 0; np < 8; np++) {
                uint32_t bh[4];
                ldm_x4(bh, vh_base + (uint32_t)(np * 16 * VSTR + kk * 16) * 2);
                mma16816(o[2 * np],     ph[kk], bh[0], bh[1]);
                mma16816(o[2 * np + 1], ph[kk], bh[2], bh[3]);
            }
        }

        c  = (c  == 2) ? 0 : c + 1;
        cn = (cn == 2) ? 0 : cn + 1;
    }

    // ---- epilogue: reduce l across the quad, scatter to original rows ----
    l0 += __shfl_xor_sync(0xffffffffu, l0, 1);
    l0 += __shfl_xor_sync(0xffffffffu, l0, 2);
    l1 += __shfl_xor_sync(0xffffffffu, l1, 1);
    l1 += __shfl_xor_sync(0xffffffffu, l1, 2);
    float il0 = 1.0f / l0, il1 = 1.0f / l1;
    #pragma unroll
    for (int nb = 0; nb < 16; nb++) {
        int dv = nb * 8 + t4 * 2;
        float2 w0 = make_float2(o[nb][0] * il0, o[nb][1] * il0);
        float2 w1 = make_float2(o[nb][2] * il1, o[nb][3] * il1);
        *(float2*)&Om[((size_t)b * Qc + prow0) * DVc + dv] = w0;
        *(float2*)&Om[((size_t)b * Qc + prow1) * DVc + dv] = w1;
    }
}

// ---------------------------------------------------------------------------
extern "C" void kernel_launch(void* const* d_in, const int* in_sizes, int n_in,
                              void* d_out, int out_size) {
    const float* q  = (const float*)d_in[0];
    const float* k  = (const float*)d_in[1];
    const float* v  = (const float*)d_in[2];
    const int*   vl = (const int*)d_in[3];
    float*       o  = (float*)d_out;

    cudaFuncSetAttribute(attn_kernel, cudaFuncAttributeMaxDynamicSharedMemorySize, SM_TOTAL);

    prep_kernel<<<PREP_GRID, 256>>>(k, v, vl);

    dim3 grid(Bc, Qc / BQ);   // x = batch (fast bid dim), y = reversed q-tile (LPT)
    attn_kernel<<<grid, 256, SM_TOTAL>>>(q, vl, o);
}